// round 9
// baseline (speedup 1.0000x reference)
#include <cuda_runtime.h>
#include <cuda_bf16.h>
#include <cstdint>
#include <math.h>

#define N_BATCH 16
#define CH 64
#define SCH 128
#define L_IN 8192
#define L_OUT 7682
#define NUM_BLOCKS 16
#define TILE_P 128
#define NTH 256

// Ping-pong fp32 residual buffers.
__device__ float g_bufA[(size_t)N_BATCH * CH * L_IN];
__device__ float g_bufB[(size_t)N_BATCH * CH * L_IN];

// Per-block pre-fragmented bf16 weights (u32 = two packed bf16, exact
// mma.sync m16n8k16 B-fragment per-lane layout):
//   Wd: [part2][kstep8][nblk8][lane32][reg2]  -> 8192 u32
//   Wr: [part2][kstep4][nblk8][lane32][reg2]  -> 4096 u32
//   Ws: [part2][kstep4][nblk16][lane32][reg2] -> 8192 u32
#define IMG_U32 20480
__device__ __align__(128) uint32_t g_Wimg[NUM_BLOCKS * IMG_U32];

// ---- shared memory layout (bytes) ----
// ldmatrix requires 16B-aligned row addresses -> strides multiple of 4 u32.
// 132 mod 32 = 4 banks/row shift, 68 mod 32 = 4: conflict-free for 8-row phases.
#define A_STRIDE_U32 132   // 128 rows x [64 u32 hi | 64 u32 lo | pad4]
#define SM_A 0
#define SM_A_BYTES (128 * A_STRIDE_U32 * 4)            // 67584
#define G_STRIDE_U32 68    // 128 rows x [32 u32 hi | 32 u32 lo | pad4]
#define SM_G SM_A_BYTES
#define SM_G_BYTES (128 * G_STRIDE_U32 * 4)            // 34816
#define SM_W (SM_G + SM_G_BYTES)                       // 102400
#define SM_WD SM_W
#define SM_WR (SM_W + 32768)
#define SM_WS (SM_W + 49152)
#define SMEM_BYTES (SM_W + 81920)                      // 184320

__device__ __forceinline__ uint32_t smem_to_u32(const void* p) {
    uint32_t a;
    asm("{ .reg .u64 t; cvta.to.shared.u64 t, %1; cvt.u32.u64 %0, t; }"
        : "=r"(a) : "l"(p));
    return a;
}

__device__ __forceinline__ void ldm_x4(uint32_t* a, uint32_t saddr) {
    asm volatile("ldmatrix.sync.aligned.m8n8.x4.shared.b16 {%0,%1,%2,%3}, [%4];"
                 : "=r"(a[0]), "=r"(a[1]), "=r"(a[2]), "=r"(a[3]) : "r"(saddr));
}

__device__ __forceinline__ void mma16816(float* d, const uint32_t* a,
                                         uint32_t b0, uint32_t b1) {
    asm volatile(
        "mma.sync.aligned.m16n8k16.row.col.f32.bf16.bf16.f32 "
        "{%0,%1,%2,%3}, {%4,%5,%6,%7}, {%8,%9}, {%0,%1,%2,%3};"
        : "+f"(d[0]), "+f"(d[1]), "+f"(d[2]), "+f"(d[3])
        : "r"(a[0]), "r"(a[1]), "r"(a[2]), "r"(a[3]), "r"(b0), "r"(b1));
}

__device__ __forceinline__ uint32_t pack2(__nv_bfloat16 a, __nv_bfloat16 b) {
    __nv_bfloat162 t(a, b);   // a -> low halfword
    return *reinterpret_cast<uint32_t*>(&t);
}

__device__ __forceinline__ void split(float x, __nv_bfloat16& h, __nv_bfloat16& l) {
    h = __float2bfloat16(x);
    l = __float2bfloat16(x - __bfloat162float(h));
}

// g = tanh(y) * sigmoid(y), via a = e^{-y}.
__device__ __forceinline__ float gated(float y) {
    float yc = fminf(fmaxf(y, -15.f), 15.f);
    float a = __expf(-yc);
    float a2 = a * a;
    return __fdividef(1.f - a2, (1.f + a2) * (1.f + a));
}

// ---------------- prep: build per-lane B fragments ----------------
__global__ void prep_weights(const float* __restrict__ Wd,
                             const float* __restrict__ Wr,
                             const float* __restrict__ Ws)
{
    int idx = blockIdx.x * blockDim.x + threadIdx.x;
    if (idx >= NUM_BLOCKS * IMG_U32) return;
    int b = idx / IMG_U32;
    int r = idx % IMG_U32;
    float w0, w1;
    int part;
    if (r < 8192) {             // Wd region
        int reg = r & 1, lane = (r >> 1) & 31, nb = (r >> 6) & 7, ks = (r >> 9) & 7;
        part = (r >> 12) & 1;
        int nn = nb * 8 + (lane >> 2), q = lane & 3;
        int k0 = ks * 16 + 2 * q + reg * 8;   // k = ch*2 + tap
        w0 = Wd[(((size_t)b * CH + nn) * CH + (k0 >> 1)) * 2 + (k0 & 1)];
        w1 = Wd[(((size_t)b * CH + nn) * CH + ((k0 + 1) >> 1)) * 2 + ((k0 + 1) & 1)];
    } else if (r < 12288) {     // Wr region
        int rr = r - 8192;
        int reg = rr & 1, lane = (rr >> 1) & 31, nb = (rr >> 6) & 7, ks = (rr >> 9) & 3;
        part = (rr >> 11) & 1;
        int nn = nb * 8 + (lane >> 2), q = lane & 3;
        int k0 = ks * 16 + 2 * q + reg * 8;
        w0 = Wr[((size_t)b * CH + nn) * CH + k0];
        w1 = Wr[((size_t)b * CH + nn) * CH + k0 + 1];
    } else {                    // Ws region
        int rr = r - 12288;
        int reg = rr & 1, lane = (rr >> 1) & 31, nb = (rr >> 6) & 15, ks = (rr >> 10) & 3;
        part = (rr >> 12) & 1;
        int nn = nb * 8 + (lane >> 2), q = lane & 3;
        int k0 = ks * 16 + 2 * q + reg * 8;
        w0 = Ws[((size_t)b * SCH + nn) * CH + k0];
        w1 = Ws[((size_t)b * SCH + nn) * CH + k0 + 1];
    }
    __nv_bfloat16 h0 = __float2bfloat16(w0);
    __nv_bfloat16 h1 = __float2bfloat16(w1);
    if (part) {
        h0 = __float2bfloat16(w0 - __bfloat162float(h0));
        h1 = __float2bfloat16(w1 - __bfloat162float(h1));
    }
    g_Wimg[(size_t)b * IMG_U32 + r] = pack2(h0, h1);
}

// ---------------- main block kernel (warp MMA) ----------------
__global__ void __launch_bounds__(NTH, 1)
wn_mma_kernel(const float* __restrict__ src, int src_stride,
              float* __restrict__ dst, int dst_stride,
              const uint32_t* __restrict__ wimg,
              float* __restrict__ skip,
              int Lcur, int d, int skip_off, int is_first)
{
    extern __shared__ unsigned char smem[];
    uint32_t* smu = reinterpret_cast<uint32_t*>(smem);
    const uint32_t smem_base = smem_to_u32(smem);
    const int tid = threadIdx.x;
    const int warp = tid >> 5, lane = tid & 31;
    const int n = blockIdx.y;
    const int p0 = blockIdx.x * TILE_P;
    const int Lnew = Lcur - d;

    // ---- copy weight fragments to smem (uint4) ----
    {
        const uint4* s = reinterpret_cast<const uint4*>(wimg);
        uint4* dsh = reinterpret_cast<uint4*>(smem + SM_W);
#pragma unroll 4
        for (int i = tid; i < IMG_U32 / 4; i += NTH) dsh[i] = s[i];
    }

    // ---- build A: [pos][k] bf16, hi u32 cols 0..63, lo 64..127 ----
    const float* srcn = src + (size_t)n * CH * src_stride;
    {
        const int pos = tid & 127, half = tid >> 7;
        const int p = p0 + pos;
        const bool v = (p < Lnew);
#pragma unroll 4
        for (int it = 0; it < 32; it++) {
            int ch = it * 2 + half;
            float x0 = v ? __ldg(srcn + (size_t)ch * src_stride + p) : 0.f;
            float x1 = v ? __ldg(srcn + (size_t)ch * src_stride + p + d) : 0.f;
            __nv_bfloat16 h0, l0, h1, l1;
            split(x0, h0, l0);
            split(x1, h1, l1);
            smu[SM_A / 4 + pos * A_STRIDE_U32 + ch] = pack2(h0, h1);        // k=2ch,2ch+1
            smu[SM_A / 4 + pos * A_STRIDE_U32 + 64 + ch] = pack2(l0, l1);
        }
    }
    __syncthreads();

    const int mrow = warp * 16 + (lane & 15);
    const int r = lane >> 2, q = lane & 3;
    const int row0 = warp * 16 + r;

    // ================= GEMM1: Y[128,64] = X2 * Wd^T (3-term) =================
    float d1[8][4];
#pragma unroll
    for (int a = 0; a < 8; a++)
#pragma unroll
        for (int k = 0; k < 4; k++) d1[a][k] = 0.f;

    {
        const uint32_t a_row = smem_base + SM_A + mrow * (A_STRIDE_U32 * 4)
                             + ((lane >> 4) * 16);
#pragma unroll
        for (int ks = 0; ks < 8; ks++) {
            uint32_t ah[4], al[4];
            ldm_x4(ah, a_row + ks * 32);
            ldm_x4(al, a_row + 256 + ks * 32);
#pragma unroll
            for (int nb = 0; nb < 8; nb++) {
                uint2 bh = *reinterpret_cast<const uint2*>(
                    smem + SM_WD + (((ks * 8 + nb) * 32 + lane) << 3));
                uint2 bl = *reinterpret_cast<const uint2*>(
                    smem + SM_WD + 16384 + (((ks * 8 + nb) * 32 + lane) << 3));
                mma16816(d1[nb], ah, bh.x, bh.y);
                mma16816(d1[nb], al, bh.x, bh.y);
                mma16816(d1[nb], ah, bl.x, bl.y);
            }
        }
    }

    // ---- epilogue 1: gated activation -> G smem (hi/lo) ----
#pragma unroll
    for (int nb = 0; nb < 8; nb++) {
        float g0 = gated(d1[nb][0]), g1 = gated(d1[nb][1]);
        float g2 = gated(d1[nb][2]), g3 = gated(d1[nb][3]);
        __nv_bfloat16 h0, l0, h1, l1, h2, l2, h3, l3;
        split(g0, h0, l0); split(g1, h1, l1);
        split(g2, h2, l2); split(g3, h3, l3);
        int col = nb * 4 + q;
        smu[SM_G / 4 + row0 * G_STRIDE_U32 + col] = pack2(h0, h1);
        smu[SM_G / 4 + row0 * G_STRIDE_U32 + 32 + col] = pack2(l0, l1);
        smu[SM_G / 4 + (row0 + 8) * G_STRIDE_U32 + col] = pack2(h2, h3);
        smu[SM_G / 4 + (row0 + 8) * G_STRIDE_U32 + 32 + col] = pack2(l2, l3);
    }
    __syncwarp();   // warp reads only its own 16 G rows below

    // ================= GEMM2: res[128,64], skip[128,128] (3-term) =================
    float dr[8][4], dsk[16][4];
#pragma unroll
    for (int a = 0; a < 8; a++)
#pragma unroll
        for (int k = 0; k < 4; k++) dr[a][k] = 0.f;
#pragma unroll
    for (int a = 0; a < 16; a++)
#pragma unroll
        for (int k = 0; k < 4; k++) dsk[a][k] = 0.f;

    {
        const uint32_t g_row = smem_base + SM_G + mrow * (G_STRIDE_U32 * 4)
                             + ((lane >> 4) * 16);
#pragma unroll
        for (int ks = 0; ks < 4; ks++) {
            uint32_t gh[4], gl[4];
            ldm_x4(gh, g_row + ks * 32);
            ldm_x4(gl, g_row + 128 + ks * 32);
#pragma unroll
            for (int nb = 0; nb < 8; nb++) {
                uint2 bh = *reinterpret_cast<const uint2*>(
                    smem + SM_WR + (((ks * 8 + nb) * 32 + lane) << 3));
                uint2 bl = *reinterpret_cast<const uint2*>(
                    smem + SM_WR + 8192 + (((ks * 8 + nb) * 32 + lane) << 3));
                mma16816(dr[nb], gh, bh.x, bh.y);
                mma16816(dr[nb], gl, bh.x, bh.y);
                mma16816(dr[nb], gh, bl.x, bl.y);
            }
#pragma unroll
            for (int nb = 0; nb < 16; nb++) {
                uint2 bh = *reinterpret_cast<const uint2*>(
                    smem + SM_WS + (((ks * 16 + nb) * 32 + lane) << 3));
                uint2 bl = *reinterpret_cast<const uint2*>(
                    smem + SM_WS + 16384 + (((ks * 16 + nb) * 32 + lane) << 3));
                mma16816(dsk[nb], gh, bh.x, bh.y);
                mma16816(dsk[nb], gl, bh.x, bh.y);
                mma16816(dsk[nb], gh, bl.x, bl.y);
            }
        }
    }
    __syncthreads();   // everyone done reading A/G before staging overwrites

    // ---- stage results to smem transposed [ch][pos] (stride 132) ----
    float* sres = reinterpret_cast<float*>(smem + SM_G);   // 64 x 132
    float* sskp = reinterpret_cast<float*>(smem + SM_A);   // 128 x 132
#pragma unroll
    for (int nb = 0; nb < 8; nb++) {
        int c = nb * 8 + 2 * q;
        sres[c * 132 + row0] = dr[nb][0];
        sres[(c + 1) * 132 + row0] = dr[nb][1];
        sres[c * 132 + row0 + 8] = dr[nb][2];
        sres[(c + 1) * 132 + row0 + 8] = dr[nb][3];
    }
#pragma unroll
    for (int nb = 0; nb < 16; nb++) {
        int c = nb * 8 + 2 * q;
        sskp[c * 132 + row0] = dsk[nb][0];
        sskp[(c + 1) * 132 + row0] = dsk[nb][1];
        sskp[c * 132 + row0 + 8] = dsk[nb][2];
        sskp[(c + 1) * 132 + row0 + 8] = dsk[nb][3];
    }
    __syncthreads();

    // ---- coalesced global stores ----
#pragma unroll 4
    for (int it = 0; it < 32; it++) {               // res: 64ch x 128pos
        int idx = it * NTH + tid;
        int c = idx >> 7, pp = idx & 127;
        int p = p0 + pp;
        if (p < Lnew) {
            float v = sres[c * 132 + pp]
                    + __ldg(srcn + (size_t)c * src_stride + p + d);
            dst[((size_t)n * CH + c) * dst_stride + p] = v;
        }
    }
    if (is_first) {
#pragma unroll 4
        for (int it = 0; it < 64; it++) {           // skip: 128ch x 128pos
            int idx = it * NTH + tid;
            int c = idx >> 7, pp = idx & 127;
            int p = p0 + pp;
            int j = p - skip_off;
            if (p < Lnew && j >= 0)
                skip[((size_t)n * SCH + c) * L_OUT + j] = sskp[c * 132 + pp];
        }
    } else {
#pragma unroll 4
        for (int it = 0; it < 64; it++) {
            int idx = it * NTH + tid;
            int c = idx >> 7, pp = idx & 127;
            int p = p0 + pp;
            int j = p - skip_off;
            if (p < Lnew && j >= 0)
                skip[((size_t)n * SCH + c) * L_OUT + j] += sskp[c * 132 + pp];
        }
    }
}

extern "C" void kernel_launch(void* const* d_in, const int* in_sizes, int n_in,
                              void* d_out, int out_size)
{
    const float* x  = (const float*)d_in[0];  // (16, 64, 8192)
    const float* Wd = (const float*)d_in[1];  // (16, 64, 64, 2)
    const float* Wr = (const float*)d_in[2];  // (16, 64, 64)
    const float* Ws = (const float*)d_in[3];  // (16, 128, 64)

    float* out  = (float*)d_out;                                   // (16, 64, 7682)
    float* skip = (float*)d_out + (size_t)N_BATCH * CH * L_OUT;    // (16, 128, 7682)

    float *bufA = nullptr, *bufB = nullptr;
    uint32_t* wimg = nullptr;
    cudaGetSymbolAddress((void**)&bufA, g_bufA);
    cudaGetSymbolAddress((void**)&bufB, g_bufB);
    cudaGetSymbolAddress((void**)&wimg, g_Wimg);
    cudaFuncSetAttribute(wn_mma_kernel,
                         cudaFuncAttributeMaxDynamicSharedMemorySize, SMEM_BYTES);

    // Build per-lane weight fragments once per replay.
    {
        int total = NUM_BLOCKS * IMG_U32;
        prep_weights<<<(total + 255) / 256, 256>>>(Wd, Wr, Ws);
    }

    const int dil[NUM_BLOCKS] = {1, 2, 4, 8, 16, 32, 64, 128,
                                 1, 2, 4, 8, 16, 32, 64, 128};

    const float* src = x;
    int src_stride = L_IN;
    int Lcur = L_IN;

    for (int i = 0; i < NUM_BLOCKS; i++) {
        int d = dil[i];
        int Lnew = Lcur - d;
        float* dst;
        int dst_stride;
        if (i == NUM_BLOCKS - 1) { dst = out; dst_stride = L_OUT; }
        else                     { dst = (i & 1) ? bufB : bufA; dst_stride = L_IN; }

        dim3 grid((Lnew + TILE_P - 1) / TILE_P, N_BATCH);
        wn_mma_kernel<<<grid, NTH, SMEM_BYTES>>>(
            src, src_stride, dst, dst_stride,
            wimg + (size_t)i * IMG_U32,
            skip, Lcur, d, Lnew - L_OUT, (i == 0) ? 1 : 0);

        src = dst;
        src_stride = dst_stride;
        Lcur = Lnew;
    }
}

// round 10
// speedup vs baseline: 1.4422x; 1.4422x over previous
#include <cuda_runtime.h>
#include <cuda_bf16.h>
#include <cstdint>
#include <math.h>

#define N_BATCH 16
#define CH 64
#define SCH 128
#define L_IN 8192
#define L_OUT 7682
#define NUM_BLOCKS 16
#define TILE_P 128
#define NTH 256

// Ping-pong fp32 residual buffers.
__device__ float g_bufA[(size_t)N_BATCH * CH * L_IN];
__device__ float g_bufB[(size_t)N_BATCH * CH * L_IN];

// Per-block pre-fragmented bf16 weights (u32 = two packed bf16, exact
// mma.sync m16n8k16 B-fragment per-lane layout), read directly via __ldg:
//   Wd: [part2][kstep8][nblk8][lane32][reg2]  -> 8192 u32 (uint2 idx 0..4095)
//   Wr: [part2][kstep4][nblk8][lane32][reg2]  -> 4096 u32 (uint2 idx 4096..6143)
//   Ws: [part2][kstep4][nblk16][lane32][reg2] -> 8192 u32 (uint2 idx 6144..10239)
#define IMG_U32 20480
__device__ __align__(128) uint32_t g_Wimg[NUM_BLOCKS * IMG_U32];

// ---- shared memory: A operand only ----
// ldmatrix needs 16B-aligned rows; stride 132 u32 (528B): 4-bank shift/row ->
// conflict-free ldmatrix phases (validated in R9).
#define A_STRIDE_U32 132
#define SMEM_BYTES (128 * A_STRIDE_U32 * 4)   // 67584

__device__ __forceinline__ uint32_t smem_to_u32(const void* p) {
    uint32_t a;
    asm("{ .reg .u64 t; cvta.to.shared.u64 t, %1; cvt.u32.u64 %0, t; }"
        : "=r"(a) : "l"(p));
    return a;
}

__device__ __forceinline__ void ldm_x4(uint32_t* a, uint32_t saddr) {
    asm volatile("ldmatrix.sync.aligned.m8n8.x4.shared.b16 {%0,%1,%2,%3}, [%4];"
                 : "=r"(a[0]), "=r"(a[1]), "=r"(a[2]), "=r"(a[3]) : "r"(saddr));
}

__device__ __forceinline__ void mma16816(float* d, const uint32_t* a,
                                         uint32_t b0, uint32_t b1) {
    asm volatile(
        "mma.sync.aligned.m16n8k16.row.col.f32.bf16.bf16.f32 "
        "{%0,%1,%2,%3}, {%4,%5,%6,%7}, {%8,%9}, {%0,%1,%2,%3};"
        : "+f"(d[0]), "+f"(d[1]), "+f"(d[2]), "+f"(d[3])
        : "r"(a[0]), "r"(a[1]), "r"(a[2]), "r"(a[3]), "r"(b0), "r"(b1));
}

__device__ __forceinline__ uint32_t pack2(__nv_bfloat16 a, __nv_bfloat16 b) {
    __nv_bfloat162 t(a, b);   // a -> low halfword
    return *reinterpret_cast<uint32_t*>(&t);
}

__device__ __forceinline__ void split(float x, __nv_bfloat16& h, __nv_bfloat16& l) {
    h = __float2bfloat16(x);
    l = __float2bfloat16(x - __bfloat162float(h));
}

// g = tanh(y) * sigmoid(y), via a = e^{-y}.
__device__ __forceinline__ float gated(float y) {
    float yc = fminf(fmaxf(y, -15.f), 15.f);
    float a = __expf(-yc);
    float a2 = a * a;
    return __fdividef(1.f - a2, (1.f + a2) * (1.f + a));
}

// ---------------- prep: build per-lane B fragments (verified in R9) ----------------
__global__ void prep_weights(const float* __restrict__ Wd,
                             const float* __restrict__ Wr,
                             const float* __restrict__ Ws)
{
    int idx = blockIdx.x * blockDim.x + threadIdx.x;
    if (idx >= NUM_BLOCKS * IMG_U32) return;
    int b = idx / IMG_U32;
    int r = idx % IMG_U32;
    float w0, w1;
    int part;
    if (r < 8192) {             // Wd region
        int reg = r & 1, lane = (r >> 1) & 31, nb = (r >> 6) & 7, ks = (r >> 9) & 7;
        part = (r >> 12) & 1;
        int nn = nb * 8 + (lane >> 2), q = lane & 3;
        int k0 = ks * 16 + 2 * q + reg * 8;   // k = ch*2 + tap
        w0 = Wd[(((size_t)b * CH + nn) * CH + (k0 >> 1)) * 2 + (k0 & 1)];
        w1 = Wd[(((size_t)b * CH + nn) * CH + ((k0 + 1) >> 1)) * 2 + ((k0 + 1) & 1)];
    } else if (r < 12288) {     // Wr region
        int rr = r - 8192;
        int reg = rr & 1, lane = (rr >> 1) & 31, nb = (rr >> 6) & 7, ks = (rr >> 9) & 3;
        part = (rr >> 11) & 1;
        int nn = nb * 8 + (lane >> 2), q = lane & 3;
        int k0 = ks * 16 + 2 * q + reg * 8;
        w0 = Wr[((size_t)b * CH + nn) * CH + k0];
        w1 = Wr[((size_t)b * CH + nn) * CH + k0 + 1];
    } else {                    // Ws region
        int rr = r - 12288;
        int reg = rr & 1, lane = (rr >> 1) & 31, nb = (rr >> 6) & 15, ks = (rr >> 10) & 3;
        part = (rr >> 12) & 1;
        int nn = nb * 8 + (lane >> 2), q = lane & 3;
        int k0 = ks * 16 + 2 * q + reg * 8;
        w0 = Ws[((size_t)b * SCH + nn) * CH + k0];
        w1 = Ws[((size_t)b * SCH + nn) * CH + k0 + 1];
    }
    __nv_bfloat16 h0 = __float2bfloat16(w0);
    __nv_bfloat16 h1 = __float2bfloat16(w1);
    if (part) {
        h0 = __float2bfloat16(w0 - __bfloat162float(h0));
        h1 = __float2bfloat16(w1 - __bfloat162float(h1));
    }
    g_Wimg[(size_t)b * IMG_U32 + r] = pack2(h0, h1);
}

// ---------------- main block kernel (warp MMA, register-resident G) ----------------
__global__ void __launch_bounds__(NTH, 2)
wn_mma_kernel(const float* __restrict__ src, int src_stride,
              float* __restrict__ dst, int dst_stride,
              const uint32_t* __restrict__ wimg,
              float* __restrict__ skip,
              int Lcur, int d, int skip_off, int is_first)
{
    extern __shared__ unsigned char smem[];
    uint32_t* smu = reinterpret_cast<uint32_t*>(smem);
    const uint32_t smem_base = smem_to_u32(smem);
    const int tid = threadIdx.x;
    const int warp = tid >> 5, lane = tid & 31;
    const int n = blockIdx.y;
    const int p0 = blockIdx.x * TILE_P;
    const int Lnew = Lcur - d;

    const uint2* w2 = reinterpret_cast<const uint2*>(wimg);
    const float* srcn = src + (size_t)n * CH * src_stride;

    // ---- build A: [pos][k] bf16, hi u32 cols 0..63, lo 64..127 ----
    {
        const int pos = tid & 127, half = tid >> 7;
        const int p = p0 + pos;
        const bool v = (p < Lnew);
#pragma unroll 4
        for (int it = 0; it < 32; it++) {
            int ch = it * 2 + half;
            float x0 = v ? __ldg(srcn + (size_t)ch * src_stride + p) : 0.f;
            float x1 = v ? __ldg(srcn + (size_t)ch * src_stride + p + d) : 0.f;
            __nv_bfloat16 h0, l0, h1, l1;
            split(x0, h0, l0);
            split(x1, h1, l1);
            smu[pos * A_STRIDE_U32 + ch] = pack2(h0, h1);        // k=2ch,2ch+1
            smu[pos * A_STRIDE_U32 + 64 + ch] = pack2(l0, l1);
        }
    }
    __syncthreads();

    const int mrow = warp * 16 + (lane & 15);
    const int r = lane >> 2, q = lane & 3;
    const int row0 = warp * 16 + r;

    // ================= GEMM1: Y[128,64] = X2 * Wd^T (3-term) =================
    float d1[8][4];
#pragma unroll
    for (int a = 0; a < 8; a++)
#pragma unroll
        for (int k = 0; k < 4; k++) d1[a][k] = 0.f;

    {
        const uint32_t a_row = smem_base + mrow * (A_STRIDE_U32 * 4)
                             + ((lane >> 4) * 16);
#pragma unroll
        for (int ks = 0; ks < 8; ks++) {
            uint32_t ah[4], al[4];
            ldm_x4(ah, a_row + ks * 32);
            ldm_x4(al, a_row + 256 + ks * 32);
#pragma unroll
            for (int nb = 0; nb < 8; nb++) {
                uint2 bh = __ldg(w2 + (ks * 8 + nb) * 32 + lane);
                uint2 bl = __ldg(w2 + 2048 + (ks * 8 + nb) * 32 + lane);
                mma16816(d1[nb], ah, bh.x, bh.y);
                mma16816(d1[nb], al, bh.x, bh.y);
                mma16816(d1[nb], ah, bl.x, bl.y);
            }
        }
    }

    // ---- epilogue 1 (registers only): gate, hi/lo split, repack as A-fragments ----
    // D-frag of GEMM1 == A-frag of GEMM2:
    //   a0 = G[r][16ks+2q..]   = d1[2ks][0..1]
    //   a1 = G[r+8][16ks+2q..] = d1[2ks][2..3]
    //   a2 = G[r][16ks+8+2q..] = d1[2ks+1][0..1]
    //   a3 = G[r+8][16ks+8+..] = d1[2ks+1][2..3]
    uint32_t gah[4][4], gal[4][4];
#pragma unroll
    for (int nb = 0; nb < 8; nb++)
#pragma unroll
        for (int k = 0; k < 4; k++) d1[nb][k] = gated(d1[nb][k]);
#pragma unroll
    for (int ks = 0; ks < 4; ks++) {
#pragma unroll
        for (int half = 0; half < 2; half++) {   // half: nb = 2ks / 2ks+1
            int nb = 2 * ks + half;
            __nv_bfloat16 h0, l0, h1, l1, h2, l2, h3, l3;
            split(d1[nb][0], h0, l0);
            split(d1[nb][1], h1, l1);
            split(d1[nb][2], h2, l2);
            split(d1[nb][3], h3, l3);
            gah[ks][2 * half]     = pack2(h0, h1);
            gah[ks][2 * half + 1] = pack2(h2, h3);
            gal[ks][2 * half]     = pack2(l0, l1);
            gal[ks][2 * half + 1] = pack2(l2, l3);
        }
    }

    const int pA = p0 + row0;
    const int pB = pA + 8;
    const bool vA = (pA < Lnew), vB = (pB < Lnew);

    // ================= GEMM2a: res[128,64] (3-term) + direct store =================
    {
        float dr[8][4];
#pragma unroll
        for (int a = 0; a < 8; a++)
#pragma unroll
            for (int k = 0; k < 4; k++) dr[a][k] = 0.f;

#pragma unroll
        for (int ks = 0; ks < 4; ks++) {
#pragma unroll
            for (int nb = 0; nb < 8; nb++) {
                uint2 bh = __ldg(w2 + 4096 + (ks * 8 + nb) * 32 + lane);
                uint2 bl = __ldg(w2 + 5120 + (ks * 8 + nb) * 32 + lane);
                mma16816(dr[nb], gah[ks], bh.x, bh.y);
                mma16816(dr[nb], gal[ks], bh.x, bh.y);
                mma16816(dr[nb], gah[ks], bl.x, bl.y);
            }
        }
        // direct store with residual add (4x32B full sectors per instr)
#pragma unroll
        for (int nb = 0; nb < 8; nb++) {
            int c = nb * 8 + 2 * q;
            if (vA) {
                dst[((size_t)n * CH + c) * dst_stride + pA] =
                    dr[nb][0] + __ldg(srcn + (size_t)c * src_stride + pA + d);
                dst[((size_t)n * CH + c + 1) * dst_stride + pA] =
                    dr[nb][1] + __ldg(srcn + (size_t)(c + 1) * src_stride + pA + d);
            }
            if (vB) {
                dst[((size_t)n * CH + c) * dst_stride + pB] =
                    dr[nb][2] + __ldg(srcn + (size_t)c * src_stride + pB + d);
                dst[((size_t)n * CH + c + 1) * dst_stride + pB] =
                    dr[nb][3] + __ldg(srcn + (size_t)(c + 1) * src_stride + pB + d);
            }
        }
    }

    // ================= GEMM2b: skip[128,128] in two n-halves =================
    const int jA = pA - skip_off;
    const int jB = pB - skip_off;
#pragma unroll
    for (int h = 0; h < 2; h++) {
        float ds[8][4];
#pragma unroll
        for (int a = 0; a < 8; a++)
#pragma unroll
            for (int k = 0; k < 4; k++) ds[a][k] = 0.f;

#pragma unroll
        for (int ks = 0; ks < 4; ks++) {
#pragma unroll
            for (int nb = 0; nb < 8; nb++) {
                int nbg = h * 8 + nb;
                uint2 bh = __ldg(w2 + 6144 + (ks * 16 + nbg) * 32 + lane);
                uint2 bl = __ldg(w2 + 8192 + (ks * 16 + nbg) * 32 + lane);
                mma16816(ds[nb], gah[ks], bh.x, bh.y);
                mma16816(ds[nb], gal[ks], bh.x, bh.y);
                mma16816(ds[nb], gah[ks], bl.x, bl.y);
            }
        }
#pragma unroll
        for (int nb = 0; nb < 8; nb++) {
            int c = h * 64 + nb * 8 + 2 * q;
            float* r0p = skip + ((size_t)n * SCH + c) * L_OUT;
            float* r1p = skip + ((size_t)n * SCH + c + 1) * L_OUT;
            if (vA && jA >= 0) {
                if (is_first) { r0p[jA] = ds[nb][0]; r1p[jA] = ds[nb][1]; }
                else          { r0p[jA] += ds[nb][0]; r1p[jA] += ds[nb][1]; }
            }
            if (vB && jB >= 0) {
                if (is_first) { r0p[jB] = ds[nb][2]; r1p[jB] = ds[nb][3]; }
                else          { r0p[jB] += ds[nb][2]; r1p[jB] += ds[nb][3]; }
            }
        }
    }
}

extern "C" void kernel_launch(void* const* d_in, const int* in_sizes, int n_in,
                              void* d_out, int out_size)
{
    const float* x  = (const float*)d_in[0];  // (16, 64, 8192)
    const float* Wd = (const float*)d_in[1];  // (16, 64, 64, 2)
    const float* Wr = (const float*)d_in[2];  // (16, 64, 64)
    const float* Ws = (const float*)d_in[3];  // (16, 128, 64)

    float* out  = (float*)d_out;                                   // (16, 64, 7682)
    float* skip = (float*)d_out + (size_t)N_BATCH * CH * L_OUT;    // (16, 128, 7682)

    float *bufA = nullptr, *bufB = nullptr;
    uint32_t* wimg = nullptr;
    cudaGetSymbolAddress((void**)&bufA, g_bufA);
    cudaGetSymbolAddress((void**)&bufB, g_bufB);
    cudaGetSymbolAddress((void**)&wimg, g_Wimg);
    cudaFuncSetAttribute(wn_mma_kernel,
                         cudaFuncAttributeMaxDynamicSharedMemorySize, SMEM_BYTES);

    // Build per-lane weight fragments once per replay.
    {
        int total = NUM_BLOCKS * IMG_U32;
        prep_weights<<<(total + 255) / 256, 256>>>(Wd, Wr, Ws);
    }

    const int dil[NUM_BLOCKS] = {1, 2, 4, 8, 16, 32, 64, 128,
                                 1, 2, 4, 8, 16, 32, 64, 128};

    const float* src = x;
    int src_stride = L_IN;
    int Lcur = L_IN;

    for (int i = 0; i < NUM_BLOCKS; i++) {
        int d = dil[i];
        int Lnew = Lcur - d;
        float* dst;
        int dst_stride;
        if (i == NUM_BLOCKS - 1) { dst = out; dst_stride = L_OUT; }
        else                     { dst = (i & 1) ? bufB : bufA; dst_stride = L_IN; }

        dim3 grid((Lnew + TILE_P - 1) / TILE_P, N_BATCH);
        wn_mma_kernel<<<grid, NTH, SMEM_BYTES>>>(
            src, src_stride, dst, dst_stride,
            wimg + (size_t)i * IMG_U32,
            skip, Lcur, d, Lnew - L_OUT, (i == 0) ? 1 : 0);

        src = dst;
        src_stride = dst_stride;
        Lcur = Lnew;
    }
}